// round 4
// baseline (speedup 1.0000x reference)
#include <cuda_runtime.h>
#include <cuda_bf16.h>

#define IN_DIM     8192
#define OUT_DIM    8192
#define NUM_GROUPS 64
#define BLOCK      256
#define ROWS_PER_BLOCK 4   // grid = 8192/4 = 2048 blocks
#define NWARP      (BLOCK / 32)

__global__ __launch_bounds__(BLOCK) void gql_kernel(
    const float* __restrict__ x,
    const float* __restrict__ w,
    const float* __restrict__ scales,
    float* __restrict__ out)
{
    __shared__ float ss[ROWS_PER_BLOCK * NUM_GROUPS];   // 1 KB: per-row group scales
    __shared__ float red[ROWS_PER_BLOCK][NWARP];

    const int tid  = threadIdx.x;
    const int row0 = blockIdx.x * ROWS_PER_BLOCK;

    // Stage this block's scales (tiny)
    if (tid < ROWS_PER_BLOCK * NUM_GROUPS)
        ss[tid] = scales[row0 * NUM_GROUPS + tid];
    __syncthreads();

    const float4* x4 = (const float4*)x;
    const float4* w0 = (const float4*)(w + (size_t)(row0 + 0) * IN_DIM);
    const float4* w1 = (const float4*)(w + (size_t)(row0 + 1) * IN_DIM);
    const float4* w2 = (const float4*)(w + (size_t)(row0 + 2) * IN_DIM);
    const float4* w3 = (const float4*)(w + (size_t)(row0 + 3) * IN_DIM);

    float acc0 = 0.f, acc1 = 0.f, acc2 = 0.f, acc3 = 0.f;

    // 8 fully-unrolled iterations; 4 rows concurrently.
    // W: streaming loads (.cs, evict-first) so the 256 MB one-pass stream does
    //    not evict x from L1. x: default-cached; L1 persists across CTAs within
    //    a launch on B300, so after warmup every block L1-hits on x.
    // Loads are issued at the top of each iteration so ptxas can front-batch a
    // large pool of independent LDG.128 (high MLP -> DRAM latency fully hidden).
    #pragma unroll
    for (int it = 0; it < IN_DIM / (4 * BLOCK); ++it) {
        const int idx = it * BLOCK + tid;      // float4 index within row
        const float4 a  = __ldcs(&w0[idx]);
        const float4 b  = __ldcs(&w1[idx]);
        const float4 c  = __ldcs(&w2[idx]);
        const float4 d  = __ldcs(&w3[idx]);
        const float4 xv = __ldg(&x4[idx]);
        const int g = idx >> 5;                // (idx*4)/128: warp-uniform group id

        const float s0 = ss[0 * NUM_GROUPS + g];
        const float s1 = ss[1 * NUM_GROUPS + g];
        const float s2 = ss[2 * NUM_GROUPS + g];
        const float s3 = ss[3 * NUM_GROUPS + g];

        // fake-quant dequant dot: round-to-nearest-even of clipped weight
        float d0 = fmaf(rintf(fminf(fmaxf(a.x, -8.f), 7.f)), xv.x,
                   fmaf(rintf(fminf(fmaxf(a.y, -8.f), 7.f)), xv.y,
                   fmaf(rintf(fminf(fmaxf(a.z, -8.f), 7.f)), xv.z,
                        rintf(fminf(fmaxf(a.w, -8.f), 7.f)) * xv.w)));
        float d1 = fmaf(rintf(fminf(fmaxf(b.x, -8.f), 7.f)), xv.x,
                   fmaf(rintf(fminf(fmaxf(b.y, -8.f), 7.f)), xv.y,
                   fmaf(rintf(fminf(fmaxf(b.z, -8.f), 7.f)), xv.z,
                        rintf(fminf(fmaxf(b.w, -8.f), 7.f)) * xv.w)));
        float d2 = fmaf(rintf(fminf(fmaxf(c.x, -8.f), 7.f)), xv.x,
                   fmaf(rintf(fminf(fmaxf(c.y, -8.f), 7.f)), xv.y,
                   fmaf(rintf(fminf(fmaxf(c.z, -8.f), 7.f)), xv.z,
                        rintf(fminf(fmaxf(c.w, -8.f), 7.f)) * xv.w)));
        float d3 = fmaf(rintf(fminf(fmaxf(d.x, -8.f), 7.f)), xv.x,
                   fmaf(rintf(fminf(fmaxf(d.y, -8.f), 7.f)), xv.y,
                   fmaf(rintf(fminf(fmaxf(d.z, -8.f), 7.f)), xv.z,
                        rintf(fminf(fmaxf(d.w, -8.f), 7.f)) * xv.w)));

        acc0 = fmaf(s0, d0, acc0);
        acc1 = fmaf(s1, d1, acc1);
        acc2 = fmaf(s2, d2, acc2);
        acc3 = fmaf(s3, d3, acc3);
    }

    // Warp reduction for all 4 accumulators
    const int lane = tid & 31;
    const int wid  = tid >> 5;
    #pragma unroll
    for (int o = 16; o; o >>= 1) {
        acc0 += __shfl_xor_sync(0xffffffffu, acc0, o);
        acc1 += __shfl_xor_sync(0xffffffffu, acc1, o);
        acc2 += __shfl_xor_sync(0xffffffffu, acc2, o);
        acc3 += __shfl_xor_sync(0xffffffffu, acc3, o);
    }
    if (lane == 0) {
        red[0][wid] = acc0;
        red[1][wid] = acc1;
        red[2][wid] = acc2;
        red[3][wid] = acc3;
    }
    __syncthreads();

    // One warp reduces: 4 rows x 8 warp-partials, segmented shuffle (8 lanes/row)
    if (tid < 32) {
        const int r = tid >> 3;          // row 0..3
        const int i = tid & 7;           // partial 0..7
        float v = red[r][i];
        v += __shfl_down_sync(0xffffffffu, v, 4);
        v += __shfl_down_sync(0xffffffffu, v, 2);
        v += __shfl_down_sync(0xffffffffu, v, 1);
        if (i == 0) out[row0 + r] = v;
    }
}

extern "C" void kernel_launch(void* const* d_in, const int* in_sizes, int n_in,
                              void* d_out, int out_size)
{
    // Resolve inputs by element count (robust to ordering):
    //   weights = 8192*8192 = 67108864, scales = 8192*64 = 524288, x = 8192
    const float* x      = nullptr;
    const float* w      = nullptr;
    const float* scales = nullptr;
    for (int i = 0; i < n_in; ++i) {
        if      (in_sizes[i] == OUT_DIM * IN_DIM)     w      = (const float*)d_in[i];
        else if (in_sizes[i] == OUT_DIM * NUM_GROUPS) scales = (const float*)d_in[i];
        else if (in_sizes[i] == IN_DIM)               x      = (const float*)d_in[i];
    }
    // Fallback to documented order if anything unmatched
    if (!x)      x      = (const float*)d_in[0];
    if (!w)      w      = (const float*)d_in[1];
    if (!scales) scales = (const float*)d_in[2];

    float* out = (float*)d_out;
    dim3 grid(OUT_DIM / ROWS_PER_BLOCK);
    gql_kernel<<<grid, BLOCK>>>(x, w, scales, out);
}

// round 8
// speedup vs baseline: 1.0894x; 1.0894x over previous
#include <cuda_runtime.h>
#include <cuda_bf16.h>

#define IN_DIM     8192
#define OUT_DIM    8192
#define NUM_GROUPS 64
#define BLOCK      256        // 8 warps; each block computes ONE output row
#define NWARP      (BLOCK / 32)
#define ITERS      (IN_DIM / (4 * BLOCK))   // 8 float4 iterations per thread

__global__ __launch_bounds__(BLOCK) void gql_kernel(
    const float* __restrict__ x,
    const float* __restrict__ w,
    const float* __restrict__ scales,
    float* __restrict__ out)
{
    __shared__ float red[NWARP];

    const int tid  = threadIdx.x;
    const int row  = blockIdx.x;
    const int wid  = tid >> 5;
    const int lane = tid & 31;

    const float4* x4 = (const float4*)x;
    const float4* w4 = (const float4*)(w + (size_t)row * IN_DIM);
    const float*  sr = scales + (size_t)row * NUM_GROUPS;

    float acc = 0.f;

    // 8 fully-unrolled iterations, one LDG.128 W stream per thread.
    // W: streaming (.cs, evict-first) so the 256 MB one-pass stream does not
    //    evict x from L1. x: default-cached; L1 persists across CTAs within a
    //    launch on B300, so after warmup every block L1-hits on x.
    // Scale index it*8+wid is warp-uniform -> one broadcast LDG per warp/iter;
    // no smem stage, no prologue barrier.
    #pragma unroll
    for (int it = 0; it < ITERS; ++it) {
        const int idx = it * BLOCK + tid;          // float4 index within row
        const float4 a  = __ldcs(&w4[idx]);
        const float4 xv = __ldg(&x4[idx]);
        const float  s  = __ldg(&sr[it * NWARP + wid]);  // group = (idx*4)/128

        float d = fmaf(rintf(fminf(fmaxf(a.x, -8.f), 7.f)), xv.x,
                  fmaf(rintf(fminf(fmaxf(a.y, -8.f), 7.f)), xv.y,
                  fmaf(rintf(fminf(fmaxf(a.z, -8.f), 7.f)), xv.z,
                       rintf(fminf(fmaxf(a.w, -8.f), 7.f)) * xv.w)));
        acc = fmaf(s, d, acc);
    }

    // Warp reduction
    #pragma unroll
    for (int o = 16; o; o >>= 1)
        acc += __shfl_xor_sync(0xffffffffu, acc, o);
    if (lane == 0) red[wid] = acc;
    __syncthreads();

    // First warp reduces the 8 warp partials
    if (tid < 32) {
        float v = (lane < NWARP) ? red[lane] : 0.f;
        v += __shfl_xor_sync(0xffffffffu, v, 4);
        v += __shfl_xor_sync(0xffffffffu, v, 2);
        v += __shfl_xor_sync(0xffffffffu, v, 1);
        if (lane == 0) out[row] = v;
    }
}

extern "C" void kernel_launch(void* const* d_in, const int* in_sizes, int n_in,
                              void* d_out, int out_size)
{
    // Resolve inputs by element count (robust to ordering):
    //   weights = 67108864, scales = 524288, x = 8192
    const float* x      = nullptr;
    const float* w      = nullptr;
    const float* scales = nullptr;
    for (int i = 0; i < n_in; ++i) {
        if      (in_sizes[i] == OUT_DIM * IN_DIM)     w      = (const float*)d_in[i];
        else if (in_sizes[i] == OUT_DIM * NUM_GROUPS) scales = (const float*)d_in[i];
        else if (in_sizes[i] == IN_DIM)               x      = (const float*)d_in[i];
    }
    if (!x)      x      = (const float*)d_in[0];
    if (!w)      w      = (const float*)d_in[1];
    if (!scales) scales = (const float*)d_in[2];

    float* out = (float*)d_out;
    gql_kernel<<<OUT_DIM, BLOCK>>>(x, w, scales, out);
}